// round 15
// baseline (speedup 1.0000x reference)
#include <cuda_runtime.h>
#include <cuda_fp16.h>
#include <cstdint>

// ============================================================================
// RetinaNet heads: pure fp16 implicit GEMM via mma.sync (HMMA) on sm_103.
// Round 15: operand loading via cp.async.bulk + mbarrier (UBLKCP). Per stage:
// 128 one-row A bulks (256 B each; halo rows from a zero page) + one B bulk
// (21760 B), replacing ~3500 per-thread cp.asyncs (LDGSTS rt=8/SMSP was the
// issue-rate cap). K=128 x 18 stages, double-buffered A+B, 2 CTAs/SM.
// Activations pre-transposed to fp16 NHWC by a DRAM-bound pre-pass.
// ============================================================================

#define NTH 256
#define C_IN 256
#define APW_TOTAL 32760
#define REG_STRIDE_N (4 * APW_TOTAL)
#define CLS_STRIDE_N (9 * APW_TOTAL)
#define CONF_BASE (16 * 4 * APW_TOTAL)

#define LDK 136                       // smem row stride in halves (272 B)
#define ROWB (LDK * 2)                // 272
#define A_ONE (128 * ROWB)            // 34816 B per A buffer
#define B_STAGE_B 21760               // 80*136*2, one B stage

#define SM_MB0 0
#define SM_MB1 8
#define A0_OFF 128
#define B_OFF (A0_OFF + 2 * A_ONE)    // 69760
#define SMEM_TOTAL (B_OFF + 2 * B_STAGE_B)   // 113280

#define TX_BYTES (128 * 256 + B_STAGE_B)     // 54528 per stage

// fp16 NHWC activations: [level-flattened img*pos][256 ch]
#define TOT_POS 87360
__device__ __align__(16) __half g_afp16[(size_t)TOT_POS * 256];
__device__ __align__(256) char g_zeros[256];          // zero page for halo rows

// B pack: [head 2][stage 18][n 80][k 136] halves (stage = tap*2 + chunk)
#define BPACK_TILE (80 * LDK)
#define BPACK_ELEMS (2 * 18 * BPACK_TILE)
__device__ __align__(16) __half g_bpack[BPACK_ELEMS];
__device__ float g_bias[2 * 80];

// ---------------------------------------------------------------------------
__device__ __forceinline__ uint32_t smem_u32(const void* p) {
    uint32_t a;
    asm("{ .reg .u64 t; cvta.to.shared.u64 t, %1; cvt.u32.u64 %0, t; }" : "=r"(a) : "l"(p));
    return a;
}
__device__ __forceinline__ void mbar_init(uint32_t a, uint32_t cnt) {
    asm volatile("mbarrier.init.shared.b64 [%0], %1;" :: "r"(a), "r"(cnt) : "memory");
}
__device__ __forceinline__ void mbar_expect(uint32_t a, uint32_t tx) {
    asm volatile("mbarrier.arrive.expect_tx.shared.b64 _, [%0], %1;" :: "r"(a), "r"(tx) : "memory");
}
__device__ __forceinline__ void mbar_wait(uint32_t a, uint32_t parity) {
    asm volatile("{\n\t.reg .pred P;\n\t"
                 "WL_%=:\n\t"
                 "mbarrier.try_wait.parity.acquire.cta.shared::cta.b64 P, [%0], %1, 0x989680;\n\t"
                 "@!P bra.uni WL_%=;\n\t}"
                 :: "r"(a), "r"(parity) : "memory");
}
__device__ __forceinline__ void bulk_g2s(uint32_t dst, const void* src, uint32_t bytes,
                                         uint32_t mbar) {
    asm volatile("cp.async.bulk.shared::cluster.global.mbarrier::complete_tx::bytes "
                 "[%0], [%1], %2, [%3];"
                 :: "r"(dst), "l"(src), "r"(bytes), "r"(mbar) : "memory");
}

__device__ __forceinline__ void ldsm_x4(uint32_t& r0, uint32_t& r1, uint32_t& r2, uint32_t& r3,
                                        uint32_t addr) {
    asm volatile("ldmatrix.sync.aligned.m8n8.x4.shared.b16 {%0,%1,%2,%3}, [%4];"
                 : "=r"(r0), "=r"(r1), "=r"(r2), "=r"(r3) : "r"(addr));
}
__device__ __forceinline__ void ldsm_x2(uint32_t& r0, uint32_t& r1, uint32_t addr) {
    asm volatile("ldmatrix.sync.aligned.m8n8.x2.shared.b16 {%0,%1}, [%2];"
                 : "=r"(r0), "=r"(r1) : "r"(addr));
}
__device__ __forceinline__ void mma_16816(float* d, const uint32_t* a, uint32_t b0, uint32_t b1) {
    asm volatile("mma.sync.aligned.m16n8k16.row.col.f32.f16.f16.f32 "
                 "{%0,%1,%2,%3}, {%4,%5,%6,%7}, {%8,%9}, {%0,%1,%2,%3};"
                 : "+f"(d[0]), "+f"(d[1]), "+f"(d[2]), "+f"(d[3])
                 : "r"(a[0]), "r"(a[1]), "r"(a[2]), "r"(a[3]), "r"(b0), "r"(b1));
}

// ---------------------------------------------------------------------------
// Transpose pre-pass: f32 NCHW -> fp16 [img*pos][256ch].
// ---------------------------------------------------------------------------
#define LDT 264
__global__ __launch_bounds__(NTH) void transpose_kernel(
    const float* __restrict__ f0, const float* __restrict__ f1,
    const float* __restrict__ f2, const float* __restrict__ f3,
    const float* __restrict__ f4, const float* __restrict__ f5)
{
    __shared__ __half tile[64 * LDT];
    int b = blockIdx.x;
    int level, tl;
    if      (b < 1024) { level = 0; tl = b;        }
    else if (b < 1280) { level = 1; tl = b - 1024; }
    else if (b < 1344) { level = 2; tl = b - 1280; }
    else if (b < 1360) { level = 3; tl = b - 1344; }
    else if (b < 1364) { level = 4; tl = b - 1360; }
    else               { level = 5; tl = b - 1364; }
    const int logW = 6 - level;
    const int HW = 1 << (2 * logW);
    const float* X = (level == 0) ? f0 : (level == 1) ? f1 : (level == 2) ? f2
                   : (level == 3) ? f3 : (level == 4) ? f4 : f5;
    const int lvl_pos_base[6] = {0, 65536, 81920, 86016, 87040, 87296};
    const int fp = tl << 6;

    const int t = threadIdx.x;
    const int px = t & 63;
    const int cg = t >> 6;

    {
        const int gp  = fp + px;
        const int img = gp >> (2 * logW);
        const int pos = gp & (HW - 1);
        const float* src = X + (size_t)img * C_IN * HW + pos;
#pragma unroll
        for (int j = 0; j < 32; j++) {
            const int ch = cg * 64 + 2 * j;
            float a  = src[(size_t)ch * HW];
            float bb = src[(size_t)(ch + 1) * HW];
            __half2 h2 = __floats2half2_rn(a, bb);
            *reinterpret_cast<__half2*>(&tile[px * LDT + ch]) = h2;
        }
    }
    __syncthreads();

    const size_t out_base = ((size_t)(lvl_pos_base[level] + fp)) << 8;
#pragma unroll
    for (int i = 0; i < 8; i++) {
        const int c = t + i * NTH;
        const int p = c >> 5, col = c & 31;
        uint4 v = *reinterpret_cast<const uint4*>(&tile[p * LDT + col * 8]);
        *reinterpret_cast<uint4*>(&g_afp16[out_base + ((size_t)p << 8) + col * 8]) = v;
    }
}

// ---------------------------------------------------------------------------
// Repack: weights -> fp16, [head][stage][n80][k136]; biases.
// ---------------------------------------------------------------------------
__global__ void repack_kernel(const float* __restrict__ wr1, const float* __restrict__ br1,
                              const float* __restrict__ wc1, const float* __restrict__ bc1,
                              const float* __restrict__ wr2, const float* __restrict__ br2,
                              const float* __restrict__ wc2, const float* __restrict__ bc2)
{
    int idx = blockIdx.x * blockDim.x + threadIdx.x;
    if (idx < BPACK_ELEMS) {
        int k     = idx % LDK;
        int n     = (idx / LDK) % 80;
        int stage = (idx / (LDK * 80)) % 18;
        int head  = idx / (LDK * 80 * 18);
        int chunk = stage & 1;
        int tap   = stage >> 1;
        float w = 0.0f;
        if (k < 128) {
            int ci = chunk * 128 + k;
            const float* wr = head ? wr2 : wr1;
            const float* wc = head ? wc2 : wc1;
            if (n < 24)      w = wr[(n * C_IN + ci) * 9 + tap];
            else if (n < 78) w = wc[((n - 24) * C_IN + ci) * 9 + tap];
        }
        g_bpack[idx] = __float2half_rn(w);
    }
    if (idx < 160) {
        int head = idx / 80, o = idx % 80;
        const float* br = head ? br2 : br1;
        const float* bc = head ? bc2 : bc1;
        float v = 0.0f;
        if (o < 24)      v = br[o];
        else if (o < 78) v = bc[o - 24];
        g_bias[idx] = v;
    }
}

// ---------------------------------------------------------------------------
__device__ __forceinline__ void store_one(float* __restrict__ out, int o, float val,
                                          int n_img, int off_l, int HW, int p, int head)
{
    float bias = g_bias[head * 80 + o];
    int idx;
    if (o < 24) {
        int c = o / 6, a = o % 6;
        idx = n_img * REG_STRIDE_N + c * APW_TOTAL + off_l + a * HW + p;
    } else {
        int oc = o - 24;
        int c = oc / 6, a = oc % 6;
        idx = CONF_BASE + n_img * CLS_STRIDE_N + c * APW_TOTAL + off_l + a * HW + p;
    }
    out[idx] = val + bias;
}

// ---------------------------------------------------------------------------
// Main kernel: 683 CTAs x 256 threads, 2 CTAs/SM.
// ---------------------------------------------------------------------------
__global__ __launch_bounds__(NTH, 2) void head_kernel(float* __restrict__ out)
{
    extern __shared__ char smem_c[];
    const uint32_t sm = smem_u32(smem_c);
    const int t = threadIdx.x;
    const int wid = t >> 5;
    const int lane = t & 31;

    // ---- block -> (level, rem) ----
    int b = blockIdx.x;
    int level, rem;
    if      (b < 512) { level = 0; rem = b;       }
    else if (b < 640) { level = 1; rem = b - 512; }
    else if (b < 672) { level = 2; rem = b - 640; }
    else if (b < 680) { level = 3; rem = b - 672; }
    else if (b < 682) { level = 4; rem = b - 680; }
    else              { level = 5; rem = b - 682; }
    const int logW = 6 - level;
    const int W  = 1 << logW;
    const int HW = 1 << (2 * logW);
    const int head = (level < 2) ? 0 : 1;
    const int lvl_off[6] = {0, 24576, 30720, 32256, 32640, 32736};
    const int lvl_pos_base[6] = {0, 65536, 81920, 86016, 87040, 87296};
    const int off_l = lvl_off[level];
    const int u0 = rem << 7;

    // ---- A bulk mapping: thread t<128 owns row t ----
    const char* cptr = nullptr;          // center pointer (512 B per position)
    uint32_t vmask = 0;                  // 9-bit tap validity
    if (t < 128) {
        const int ur = u0 + t;
        const bool ok = ur < (HW << 4);
        const int posr = ur & (HW - 1);
        const int h0 = posr >> logW;
        const int w0 = posr & (W - 1);
        cptr = (const char*)(g_afp16 + (((size_t)(lvl_pos_base[level] + ur)) << 8));
        if (ok) {
#pragma unroll
            for (int tap = 0; tap < 9; tap++) {
                const int hh = h0 + tap / 3 - 1, ww = w0 + tap % 3 - 1;
                if ((unsigned)hh < (unsigned)W && (unsigned)ww < (unsigned)W)
                    vmask |= (1u << tap);
            }
        }
    }

    // ---- MMA mapping: warp grid 4(M) x 2(N), warp tile m32 x n40 ----
    const int wm = (wid & 3) << 5;
    const int wn = (wid >> 2) * 40;
    const int arow = lane & 15, acol = lane >> 4;
    const int brow4 = (lane & 7) + ((lane >> 4) << 3), bcol4 = (lane >> 3) & 1;
    const int brow2 = (lane & 7), bcol2 = (lane >> 3) & 1;

    float acc[2][5][4];
#pragma unroll
    for (int i = 0; i < 2; i++)
#pragma unroll
        for (int j = 0; j < 5; j++)
#pragma unroll
            for (int r = 0; r < 4; r++) acc[i][j][r] = 0.0f;

    const char* bpack_base = (const char*)(g_bpack) +
        (size_t)(head * 18) * BPACK_TILE * sizeof(__half);

    // ---- prologue: init mbarriers, arm both phases, issue stage-0 bulks ----
    if (t == 0) { mbar_init(sm + SM_MB0, 1); mbar_init(sm + SM_MB1, 1); }
    __syncthreads();
    if (t == 0) { mbar_expect(sm + SM_MB0, TX_BYTES); mbar_expect(sm + SM_MB1, TX_BYTES); }
    __syncthreads();          // expects visible before any bulk

    {
        // stage 0: tap 0, chunk 0; tap offset = (-W-1)*512 bytes
        if (t < 128) {
            const void* src = (vmask & 1u) ? (const void*)(cptr + (-W - 1) * 512)
                                           : (const void*)g_zeros;
            bulk_g2s(sm + A0_OFF + t * ROWB, src, 256, sm + SM_MB0);
        } else if (t == 128) {
            bulk_g2s(sm + B_OFF, bpack_base, B_STAGE_B, sm + SM_MB0);
        }
    }

    int ph0 = 0, ph1 = 0;

    for (int s = 0; s < 18; ++s) {
        // ---- issue bulks for stage s+1 into the other buffers ----
        if (s + 1 < 18) {
            const int sn = s + 1;
            const int tap = sn >> 1;
            const int tapoff = ((tap / 3 - 1) * W + (tap % 3 - 1)) * 512 + (sn & 1) * 256;
            const uint32_t mb = sm + ((sn & 1) ? SM_MB1 : SM_MB0);
            if (t < 128) {
                const void* src = ((vmask >> tap) & 1u) ? (const void*)(cptr + tapoff)
                                                        : (const void*)g_zeros;
                bulk_g2s(sm + A0_OFF + ((sn & 1) ? A_ONE : 0) + t * ROWB, src, 256, mb);
            } else if (t == 128) {
                bulk_g2s(sm + B_OFF + ((sn & 1) ? B_STAGE_B : 0),
                         bpack_base + (size_t)sn * B_STAGE_B, B_STAGE_B, mb);
            }
        }

        // ---- wait stage-s data ----
        if (s & 1) { mbar_wait(sm + SM_MB1, ph1); ph1 ^= 1; }
        else       { mbar_wait(sm + SM_MB0, ph0); ph0 ^= 1; }

        // ---- MMA(s): 8 k16 steps ----
        const uint32_t abuf = sm + A0_OFF + ((s & 1) ? A_ONE : 0);
        const uint32_t bbuf = sm + B_OFF + ((s & 1) ? B_STAGE_B : 0);
#pragma unroll
        for (int ks = 0; ks < 8; ks++) {
            const int kb = ks * 32;

            uint32_t ah[2][4];
#pragma unroll
            for (int mi = 0; mi < 2; mi++) {
                uint32_t ad = abuf + (wm + mi * 16 + arow) * ROWB + kb + acol * 16;
                ldsm_x4(ah[mi][0], ah[mi][1], ah[mi][2], ah[mi][3], ad);
            }

            uint32_t bh[10];
            {
                uint32_t b0 = bbuf + kb;
                ldsm_x4(bh[0], bh[1], bh[2], bh[3], b0 + (wn + brow4) * ROWB + bcol4 * 16);
                ldsm_x4(bh[4], bh[5], bh[6], bh[7], b0 + (wn + 16 + brow4) * ROWB + bcol4 * 16);
                ldsm_x2(bh[8], bh[9],             b0 + (wn + 32 + brow2) * ROWB + bcol2 * 16);
            }
#pragma unroll
            for (int mi = 0; mi < 2; mi++)
#pragma unroll
                for (int nj = 0; nj < 5; nj++)
                    mma_16816(acc[mi][nj], ah[mi], bh[2 * nj], bh[2 * nj + 1]);
        }

        // ---- arm phase for stage s+2 (ordered before its bulks by the sync) ----
        if (s < 16 && t == 0)
            mbar_expect(sm + ((s & 1) ? SM_MB1 : SM_MB0), TX_BYTES);

        __syncthreads();   // readers of stage s done; buffer (s)&1 free for s+2 bulks
    }

    // ---- epilogue: bias + scatter ----
#pragma unroll
    for (int mi = 0; mi < 2; mi++) {
        const int ur0 = u0 + wm + mi * 16 + (lane >> 2);
#pragma unroll
        for (int half = 0; half < 2; half++) {
            const int ur = ur0 + half * 8;
            if (ur >= (HW << 4)) continue;
            const int img_e = ur >> (2 * logW);
            const int p_e   = ur & (HW - 1);
#pragma unroll
            for (int nj = 0; nj < 5; nj++) {
                const int o0 = wn + nj * 8 + (lane & 3) * 2;
                const float v0 = acc[mi][nj][half * 2];
                const float v1 = acc[mi][nj][half * 2 + 1];
                if (o0 < 78)     store_one(out, o0,     v0, img_e, off_l, HW, p_e, head);
                if (o0 + 1 < 78) store_one(out, o0 + 1, v1, img_e, off_l, HW, p_e, head);
            }
        }
    }
}

// ---------------------------------------------------------------------------
extern "C" void kernel_launch(void* const* d_in, const int* in_sizes, int n_in,
                              void* d_out, int out_size)
{
    cudaFuncSetAttribute(head_kernel, cudaFuncAttributeMaxDynamicSharedMemorySize, SMEM_TOTAL);

    transpose_kernel<<<1365, NTH>>>(
        (const float*)d_in[0], (const float*)d_in[1], (const float*)d_in[2],
        (const float*)d_in[3], (const float*)d_in[4], (const float*)d_in[5]);

    repack_kernel<<<(BPACK_ELEMS + NTH - 1) / NTH, NTH>>>(
        (const float*)d_in[6],  (const float*)d_in[7],
        (const float*)d_in[8],  (const float*)d_in[9],
        (const float*)d_in[10], (const float*)d_in[11],
        (const float*)d_in[12], (const float*)d_in[13]);

    head_kernel<<<683, NTH, SMEM_TOTAL>>>((float*)d_out);
}